// round 1
// baseline (speedup 1.0000x reference)
#include <cuda_runtime.h>
#include <math.h>

// ---------------- problem constants (fixed for this instance) ----------------
#define B_CONST 2
#define H_NUM   16
#define HD      32
// E, T, S derived at launch from in_sizes (E from bias size).

// ---------------- device scratch (no cudaMalloc allowed) ----------------
__device__ float g_q [2*2048*512];
__device__ float g_k [2*2048*512];
__device__ float g_v [2*2048*512];
__device__ float g_ao[2*2048*512];
__device__ unsigned char g_gflag[4096];

// ---------------- global-token column flags (matches np.linspace trunc) -----
__global__ void gflags_kernel(int S, const int* __restrict__ Gptr) {
    int j = blockIdx.x * blockDim.x + threadIdx.x;
    if (j >= S) return;
    int G = *Gptr;
    unsigned char f = 0;
    if (G > 0) {
        int stride = S / (G + 1);
        if (G == 1) {
            if (j == stride) f = 1;
        } else {
            double stp = (double)(S - 2 * stride) / (double)(G - 1);
            for (int t = 0; t < G; t++) {
                long long gi = (t == G - 1)
                    ? (long long)(S - stride)
                    : (long long)((double)t * stp + (double)stride);
                if ((long long)j == gi) f = 1;
            }
        }
    }
    g_gflag[j] = f;
}

// ---------------- tiled fp32 GEMM: C = (A @ W^T + bias) * alpha -------------
// A: [M,K] row-major, W: [N,K] row-major, C: [M,N] row-major.
#define GBM 128
#define GBN 64
#define GBK 16
#define GTM 8
#define GTN 4
// 256 threads, each computes 8x4.

__global__ __launch_bounds__(256)
void gemm_bias_kernel(const float* __restrict__ A, const float* __restrict__ W,
                      const float* __restrict__ bias, float* __restrict__ C,
                      int M, int N, int K, float alpha_s,
                      const float* __restrict__ alpha_ptr) {
    __shared__ float As[GBK][GBM];
    __shared__ float Bs[GBK][GBN];
    int tid = threadIdx.x;
    int bm = blockIdx.y * GBM;
    int bn = blockIdx.x * GBN;
    int tx = tid % (GBN / GTN);   // 0..15
    int ty = tid / (GBN / GTN);   // 0..15

    float acc[GTM][GTN];
#pragma unroll
    for (int i = 0; i < GTM; i++)
#pragma unroll
        for (int j = 0; j < GTN; j++) acc[i][j] = 0.f;

    int lrow = tid >> 2;          // 0..63
    int lk   = (tid & 3) * 4;     // 0,4,8,12

    for (int k0 = 0; k0 < K; k0 += GBK) {
#pragma unroll
        for (int r = 0; r < GBM; r += 64) {
            float4 v = *(const float4*)(A + (size_t)(bm + lrow + r) * K + k0 + lk);
            As[lk + 0][lrow + r] = v.x;
            As[lk + 1][lrow + r] = v.y;
            As[lk + 2][lrow + r] = v.z;
            As[lk + 3][lrow + r] = v.w;
        }
        {
            float4 v = *(const float4*)(W + (size_t)(bn + lrow) * K + k0 + lk);
            Bs[lk + 0][lrow] = v.x;
            Bs[lk + 1][lrow] = v.y;
            Bs[lk + 2][lrow] = v.z;
            Bs[lk + 3][lrow] = v.w;
        }
        __syncthreads();
#pragma unroll
        for (int k = 0; k < GBK; k++) {
            float a[GTM], b[GTN];
            *(float4*)&a[0] = *(const float4*)&As[k][ty * GTM];
            *(float4*)&a[4] = *(const float4*)&As[k][ty * GTM + 4];
            *(float4*)&b[0] = *(const float4*)&Bs[k][tx * GTN];
#pragma unroll
            for (int i = 0; i < GTM; i++)
#pragma unroll
                for (int j = 0; j < GTN; j++) acc[i][j] += a[i] * b[j];
        }
        __syncthreads();
    }

    float alpha = alpha_s;
    if (alpha_ptr) alpha *= *alpha_ptr;
    float4 bb = *(const float4*)(bias + bn + tx * GTN);
#pragma unroll
    for (int i = 0; i < GTM; i++) {
        int row = bm + ty * GTM + i;
        float4 o;
        o.x = (acc[i][0] + bb.x) * alpha;
        o.y = (acc[i][1] + bb.y) * alpha;
        o.z = (acc[i][2] + bb.z) * alpha;
        o.w = (acc[i][3] + bb.w) * alpha;
        *(float4*)(C + (size_t)row * N + bn + tx * GTN) = o;
    }
}

// ---------------- sparse flash attention ------------------------------------
// grid: (T/AT_BM, H, B), 128 threads; thread t owns query row i0+t of head h.
#define AT_BM 128
#define AT_BN 64
#define KS_STR 36   // padded row stride for K/V tiles (bank-conflict relief)

__global__ __launch_bounds__(128)
void sparse_attn_kernel(int T, int S, int E,
                        const int* __restrict__ Wptr,
                        const int* __restrict__ Gptr) {
    extern __shared__ float sm[];
    float* Ks = sm;                          // [AT_BN][KS_STR]
    float* Vs = sm + AT_BN * KS_STR;         // [AT_BN][KS_STR]
    float* Ss = Vs + AT_BN * KS_STR;         // [AT_BN][AT_BM] transposed scores
    unsigned char* Fl = (unsigned char*)(Ss + AT_BN * AT_BM); // [AT_BN]

    int b = blockIdx.z, h = blockIdx.y;
    int i0 = blockIdx.x * AT_BM;
    int t = threadIdx.x;
    int i = i0 + t;

    const float* qrow = g_q + ((size_t)(b * T + i)) * E + h * HD;
    float qreg[HD];
#pragma unroll
    for (int d4 = 0; d4 < HD / 4; d4++) {
        float4 v = *(const float4*)(qrow + d4 * 4);
        qreg[d4 * 4 + 0] = v.x; qreg[d4 * 4 + 1] = v.y;
        qreg[d4 * 4 + 2] = v.z; qreg[d4 * 4 + 3] = v.w;
    }

    float mrow = -INFINITY, l = 0.f;
    float acc[HD];
#pragma unroll
    for (int d = 0; d < HD; d++) acc[d] = 0.f;

    int Wl = *Wptr, G = *Gptr;
    (void)G;
    int ov = Wl / 4, step = Wl - ov, halfw = Wl / 2;

    // per-row block-window column range (union of <=2 overlapping blocks is contiguous)
    int klo = (i >= Wl) ? (i - Wl) / step + 1 : 0;
    int khi = i / step;
    int blo = klo * step - ov;          // inclusive (j>=0 clamps naturally)
    int bhi = khi * step + Wl + ov;     // exclusive

    // CTA-wide ranges for tile skipping
    int ctaw_lo = i0 - halfw, ctaw_hi = i0 + AT_BM - 1 + halfw;
    int cklo = (i0 >= Wl) ? (i0 - Wl) / step + 1 : 0;
    int ckhi = (i0 + AT_BM - 1) / step;
    int cblo = cklo * step - ov, cbhi = ckhi * step + Wl + ov;

    const float* kbase = g_k + (size_t)b * S * E + h * HD;
    const float* vbase = g_v + (size_t)b * S * E + h * HD;

    for (int j0 = 0; j0 < S; j0 += AT_BN) {
        bool anyg = (t < AT_BN) && g_gflag[j0 + t];
        bool overlap = (j0 + AT_BN - 1 >= ctaw_lo && j0 <= ctaw_hi) ||
                       (j0 + AT_BN - 1 >= cblo   && j0 <  cbhi);
        int active = __syncthreads_or((int)(anyg || overlap));
        if (!active) continue;

        // load K/V tile: thread t -> row t/2, half (t&1)*16 (coalesced 64B runs)
        {
            int row = t >> 1, half = (t & 1) * 16;
            const float* kp = kbase + (size_t)(j0 + row) * E + half;
            const float* vp = vbase + (size_t)(j0 + row) * E + half;
#pragma unroll
            for (int c = 0; c < 16; c += 4) {
                *(float4*)&Ks[row * KS_STR + half + c] = *(const float4*)(kp + c);
                *(float4*)&Vs[row * KS_STR + half + c] = *(const float4*)(vp + c);
            }
            if (t < AT_BN) Fl[t] = g_gflag[j0 + t];
        }
        __syncthreads();

        float tmax = -INFINITY;
        for (int jj = 0; jj < AT_BN; jj++) {
            int j = j0 + jj;
            bool msk = (j >= i - halfw && j <= i + halfw) ||
                       (j >= blo && j < bhi) || Fl[jj];
            float s = -INFINITY;
            if (msk) {
                const float4* kr = (const float4*)&Ks[jj * KS_STR];
                float s0 = 0.f, s1 = 0.f, s2 = 0.f, s3 = 0.f;
#pragma unroll
                for (int d4 = 0; d4 < 8; d4++) {
                    float4 kk = kr[d4];
                    s0 += qreg[d4 * 4 + 0] * kk.x;
                    s1 += qreg[d4 * 4 + 1] * kk.y;
                    s2 += qreg[d4 * 4 + 2] * kk.z;
                    s3 += qreg[d4 * 4 + 3] * kk.w;
                }
                s = (s0 + s1) + (s2 + s3);
                tmax = fmaxf(tmax, s);
            }
            Ss[jj * AT_BM + t] = s;
        }

        if (tmax > -INFINITY) {     // guard avoids -inf - -inf = NaN
            float mnew = fmaxf(mrow, tmax);
            float cscale = __expf(mrow - mnew);  // 0 on first active tile
            mrow = mnew;
            l *= cscale;
#pragma unroll
            for (int d = 0; d < HD; d++) acc[d] *= cscale;
            for (int jj = 0; jj < AT_BN; jj++) {
                float p = __expf(Ss[jj * AT_BM + t] - mnew);  // masked -> 0
                l += p;
                const float4* vr = (const float4*)&Vs[jj * KS_STR];
#pragma unroll
                for (int d4 = 0; d4 < 8; d4++) {
                    float4 vv = vr[d4];
                    acc[d4 * 4 + 0] += p * vv.x;
                    acc[d4 * 4 + 1] += p * vv.y;
                    acc[d4 * 4 + 2] += p * vv.z;
                    acc[d4 * 4 + 3] += p * vv.w;
                }
            }
        }
        __syncthreads();
    }

    float inv = 1.0f / l;   // every row has diagonal unmasked -> l > 0
    float* orow = g_ao + ((size_t)(b * T + i)) * E + h * HD;
#pragma unroll
    for (int d4 = 0; d4 < 8; d4++) {
        float4 o;
        o.x = acc[d4 * 4 + 0] * inv;
        o.y = acc[d4 * 4 + 1] * inv;
        o.z = acc[d4 * 4 + 2] * inv;
        o.w = acc[d4 * 4 + 3] * inv;
        *(float4*)(orow + d4 * 4) = o;
    }
}

// ---------------- launch -----------------------------------------------------
#define ATT_SMEM (AT_BN * KS_STR * 4 * 2 + AT_BN * AT_BM * 4 + AT_BN + 64)

extern "C" void kernel_launch(void* const* d_in, const int* in_sizes, int n_in,
                              void* d_out, int out_size) {
    const float* query = (const float*)d_in[0];
    const float* key_  = (const float*)d_in[1];
    const float* value = (const float*)d_in[2];
    const float* Wq = (const float*)d_in[3];
    const float* bq = (const float*)d_in[4];
    const float* Wk = (const float*)d_in[5];
    const float* bk = (const float*)d_in[6];
    const float* Wv = (const float*)d_in[7];
    const float* bv = (const float*)d_in[8];
    const float* Wo = (const float*)d_in[9];
    const float* bo = (const float*)d_in[10];
    const float* temperature = (const float*)d_in[11];
    const int* wsize = (const int*)d_in[12];
    const int* gnum  = (const int*)d_in[13];
    float* out = (float*)d_out;

    int E = in_sizes[4];                 // 512
    int B = B_CONST;
    int T = in_sizes[0] / (B * E);       // 2048
    int S = in_sizes[1] / (B * E);       // 2048
    int M = B * T;                       // 4096
    int hd = E / H_NUM;

    float *qb, *kb, *vb, *aob;
    cudaGetSymbolAddress((void**)&qb,  g_q);
    cudaGetSymbolAddress((void**)&kb,  g_k);
    cudaGetSymbolAddress((void**)&vb,  g_v);
    cudaGetSymbolAddress((void**)&aob, g_ao);

    // global-token column flags
    gflags_kernel<<<(S + 255) / 256, 256>>>(S, gnum);

    dim3 ggrid(E / GBN, M / GBM);
    float scaling = 1.0f / sqrtf((float)hd);
    // q projection with hd^-0.5 * temperature folded in
    gemm_bias_kernel<<<ggrid, 256>>>(query, Wq, bq, qb, M, E, E, scaling, temperature);
    gemm_bias_kernel<<<ggrid, 256>>>(key_,  Wk, bk, kb, M, E, E, 1.0f, nullptr);
    gemm_bias_kernel<<<ggrid, 256>>>(value, Wv, bv, vb, M, E, E, 1.0f, nullptr);

    cudaFuncSetAttribute(sparse_attn_kernel,
                         cudaFuncAttributeMaxDynamicSharedMemorySize, ATT_SMEM);
    sparse_attn_kernel<<<dim3(T / AT_BM, H_NUM, B), 128, ATT_SMEM>>>(T, S, E, wsize, gnum);

    gemm_bias_kernel<<<ggrid, 256>>>(aob, Wo, bo, out, M, E, E, 1.0f, nullptr);
}

// round 2
// speedup vs baseline: 1.6232x; 1.6232x over previous
#include <cuda_runtime.h>
#include <math.h>

// ---------------- problem constants (fixed for this instance) ----------------
#define B_CONST 2
#define H_NUM   16
#define HD      32
// E, T, S derived at launch from in_sizes (E from bias size).

// ---------------- device scratch (no cudaMalloc allowed) ----------------
__device__ float g_q [2*2048*512];
__device__ float g_k [2*2048*512];
__device__ float g_v [2*2048*512];
__device__ float g_ao[2*2048*512];
__device__ unsigned char g_gflag[4096];

// ---------------- global-token column flags (matches np.linspace trunc) -----
__global__ void gflags_kernel(int S, const int* __restrict__ Gptr) {
    int j = blockIdx.x * blockDim.x + threadIdx.x;
    if (j >= S) return;
    int G = *Gptr;
    unsigned char f = 0;
    if (G > 0) {
        int stride = S / (G + 1);
        if (G == 1) {
            if (j == stride) f = 1;
        } else {
            double stp = (double)(S - 2 * stride) / (double)(G - 1);
            for (int t = 0; t < G; t++) {
                long long gi = (t == G - 1)
                    ? (long long)(S - stride)
                    : (long long)((double)t * stp + (double)stride);
                if ((long long)j == gi) f = 1;
            }
        }
    }
    g_gflag[j] = f;
}

// ---------------- tiled fp32 GEMM: C = (A @ W^T + bias) * alpha -------------
// A: [M,K] row-major, W: [N,K] row-major, C: [M,N] row-major.
#define GBM 128
#define GBN 64
#define GBK 16
#define GTM 8
#define GTN 4
// 256 threads, each computes 8x4.

__global__ __launch_bounds__(256)
void gemm_bias_kernel(const float* __restrict__ A, const float* __restrict__ W,
                      const float* __restrict__ bias, float* __restrict__ C,
                      int M, int N, int K, float alpha_s,
                      const float* __restrict__ alpha_ptr) {
    __shared__ float As[GBK][GBM];
    __shared__ float Bs[GBK][GBN];
    int tid = threadIdx.x;
    int bm = blockIdx.y * GBM;
    int bn = blockIdx.x * GBN;
    int tx = tid % (GBN / GTN);   // 0..15
    int ty = tid / (GBN / GTN);   // 0..15

    float acc[GTM][GTN];
#pragma unroll
    for (int i = 0; i < GTM; i++)
#pragma unroll
        for (int j = 0; j < GTN; j++) acc[i][j] = 0.f;

    int lrow = tid >> 2;          // 0..63
    int lk   = (tid & 3) * 4;     // 0,4,8,12

    for (int k0 = 0; k0 < K; k0 += GBK) {
#pragma unroll
        for (int r = 0; r < GBM; r += 64) {
            float4 v = *(const float4*)(A + (size_t)(bm + lrow + r) * K + k0 + lk);
            As[lk + 0][lrow + r] = v.x;
            As[lk + 1][lrow + r] = v.y;
            As[lk + 2][lrow + r] = v.z;
            As[lk + 3][lrow + r] = v.w;
        }
        {
            float4 v = *(const float4*)(W + (size_t)(bn + lrow) * K + k0 + lk);
            Bs[lk + 0][lrow] = v.x;
            Bs[lk + 1][lrow] = v.y;
            Bs[lk + 2][lrow] = v.z;
            Bs[lk + 3][lrow] = v.w;
        }
        __syncthreads();
#pragma unroll
        for (int k = 0; k < GBK; k++) {
            float a[GTM], b[GTN];
            *(float4*)&a[0] = *(const float4*)&As[k][ty * GTM];
            *(float4*)&a[4] = *(const float4*)&As[k][ty * GTM + 4];
            *(float4*)&b[0] = *(const float4*)&Bs[k][tx * GTN];
#pragma unroll
            for (int i = 0; i < GTM; i++)
#pragma unroll
                for (int j = 0; j < GTN; j++) acc[i][j] += a[i] * b[j];
        }
        __syncthreads();
    }

    float alpha = alpha_s;
    if (alpha_ptr) alpha *= *alpha_ptr;
    float4 bb = *(const float4*)(bias + bn + tx * GTN);
#pragma unroll
    for (int i = 0; i < GTM; i++) {
        int row = bm + ty * GTM + i;
        float4 o;
        o.x = (acc[i][0] + bb.x) * alpha;
        o.y = (acc[i][1] + bb.y) * alpha;
        o.z = (acc[i][2] + bb.z) * alpha;
        o.w = (acc[i][3] + bb.w) * alpha;
        *(float4*)(C + (size_t)row * N + bn + tx * GTN) = o;
    }
}

// ---------------- sparse flash attention ------------------------------------
// grid: (T/AT_BM, H, B), 128 threads; thread t owns query row i0+t of head h.
#define AT_BM 128
#define AT_BN 64
#define KS_STR 36   // padded row stride for K/V tiles (bank-conflict relief)

__global__ __launch_bounds__(128)
void sparse_attn_kernel(int T, int S, int E,
                        const int* __restrict__ Wptr,
                        const int* __restrict__ Gptr) {
    extern __shared__ float sm[];
    float* Ks = sm;                          // [AT_BN][KS_STR]
    float* Vs = sm + AT_BN * KS_STR;         // [AT_BN][KS_STR]
    float* Ss = Vs + AT_BN * KS_STR;         // [AT_BN][AT_BM] transposed scores
    unsigned char* Fl = (unsigned char*)(Ss + AT_BN * AT_BM); // [AT_BN]

    int b = blockIdx.z, h = blockIdx.y;
    int i0 = blockIdx.x * AT_BM;
    int t = threadIdx.x;
    int i = i0 + t;

    const float* qrow = g_q + ((size_t)(b * T + i)) * E + h * HD;
    float qreg[HD];
#pragma unroll
    for (int d4 = 0; d4 < HD / 4; d4++) {
        float4 v = *(const float4*)(qrow + d4 * 4);
        qreg[d4 * 4 + 0] = v.x; qreg[d4 * 4 + 1] = v.y;
        qreg[d4 * 4 + 2] = v.z; qreg[d4 * 4 + 3] = v.w;
    }

    float mrow = -INFINITY, l = 0.f;
    float acc[HD];
#pragma unroll
    for (int d = 0; d < HD; d++) acc[d] = 0.f;

    int Wl = *Wptr, G = *Gptr;
    (void)G;
    int ov = Wl / 4, step = Wl - ov, halfw = Wl / 2;

    // per-row block-window column range (union of <=2 overlapping blocks is contiguous)
    int klo = (i >= Wl) ? (i - Wl) / step + 1 : 0;
    int khi = i / step;
    int blo = klo * step - ov;          // inclusive (j>=0 clamps naturally)
    int bhi = khi * step + Wl + ov;     // exclusive

    // CTA-wide ranges for tile skipping
    int ctaw_lo = i0 - halfw, ctaw_hi = i0 + AT_BM - 1 + halfw;
    int cklo = (i0 >= Wl) ? (i0 - Wl) / step + 1 : 0;
    int ckhi = (i0 + AT_BM - 1) / step;
    int cblo = cklo * step - ov, cbhi = ckhi * step + Wl + ov;

    const float* kbase = g_k + (size_t)b * S * E + h * HD;
    const float* vbase = g_v + (size_t)b * S * E + h * HD;

    for (int j0 = 0; j0 < S; j0 += AT_BN) {
        bool anyg = (t < AT_BN) && g_gflag[j0 + t];
        bool overlap = (j0 + AT_BN - 1 >= ctaw_lo && j0 <= ctaw_hi) ||
                       (j0 + AT_BN - 1 >= cblo   && j0 <  cbhi);
        int active = __syncthreads_or((int)(anyg || overlap));
        if (!active) continue;

        // load K/V tile: thread t -> row t/2, half (t&1)*16 (coalesced 64B runs)
        {
            int row = t >> 1, half = (t & 1) * 16;
            const float* kp = kbase + (size_t)(j0 + row) * E + half;
            const float* vp = vbase + (size_t)(j0 + row) * E + half;
#pragma unroll
            for (int c = 0; c < 16; c += 4) {
                *(float4*)&Ks[row * KS_STR + half + c] = *(const float4*)(kp + c);
                *(float4*)&Vs[row * KS_STR + half + c] = *(const float4*)(vp + c);
            }
            if (t < AT_BN) Fl[t] = g_gflag[j0 + t];
        }
        __syncthreads();

        float tmax = -INFINITY;
        for (int jj = 0; jj < AT_BN; jj++) {
            int j = j0 + jj;
            bool msk = (j >= i - halfw && j <= i + halfw) ||
                       (j >= blo && j < bhi) || Fl[jj];
            float s = -INFINITY;
            if (msk) {
                const float4* kr = (const float4*)&Ks[jj * KS_STR];
                float s0 = 0.f, s1 = 0.f, s2 = 0.f, s3 = 0.f;
#pragma unroll
                for (int d4 = 0; d4 < 8; d4++) {
                    float4 kk = kr[d4];
                    s0 += qreg[d4 * 4 + 0] * kk.x;
                    s1 += qreg[d4 * 4 + 1] * kk.y;
                    s2 += qreg[d4 * 4 + 2] * kk.z;
                    s3 += qreg[d4 * 4 + 3] * kk.w;
                }
                s = (s0 + s1) + (s2 + s3);
                tmax = fmaxf(tmax, s);
            }
            Ss[jj * AT_BM + t] = s;
        }

        if (tmax > -INFINITY) {     // guard avoids -inf - -inf = NaN
            float mnew = fmaxf(mrow, tmax);
            float cscale = __expf(mrow - mnew);  // 0 on first active tile
            mrow = mnew;
            l *= cscale;
#pragma unroll
            for (int d = 0; d < HD; d++) acc[d] *= cscale;
            for (int jj = 0; jj < AT_BN; jj++) {
                float p = __expf(Ss[jj * AT_BM + t] - mnew);  // masked -> 0
                l += p;
                const float4* vr = (const float4*)&Vs[jj * KS_STR];
#pragma unroll
                for (int d4 = 0; d4 < 8; d4++) {
                    float4 vv = vr[d4];
                    acc[d4 * 4 + 0] += p * vv.x;
                    acc[d4 * 4 + 1] += p * vv.y;
                    acc[d4 * 4 + 2] += p * vv.z;
                    acc[d4 * 4 + 3] += p * vv.w;
                }
            }
        }
        __syncthreads();
    }

    float inv = 1.0f / l;   // every row has diagonal unmasked -> l > 0
    float* orow = g_ao + ((size_t)(b * T + i)) * E + h * HD;
#pragma unroll
    for (int d4 = 0; d4 < 8; d4++) {
        float4 o;
        o.x = acc[d4 * 4 + 0] * inv;
        o.y = acc[d4 * 4 + 1] * inv;
        o.z = acc[d4 * 4 + 2] * inv;
        o.w = acc[d4 * 4 + 3] * inv;
        *(float4*)(orow + d4 * 4) = o;
    }
}

// ---------------- launch -----------------------------------------------------
#define ATT_SMEM (AT_BN * KS_STR * 4 * 2 + AT_BN * AT_BM * 4 + AT_BN + 64)

extern "C" void kernel_launch(void* const* d_in, const int* in_sizes, int n_in,
                              void* d_out, int out_size) {
    const float* query = (const float*)d_in[0];
    const float* key_  = (const float*)d_in[1];
    const float* value = (const float*)d_in[2];
    const float* Wq = (const float*)d_in[3];
    const float* bq = (const float*)d_in[4];
    const float* Wk = (const float*)d_in[5];
    const float* bk = (const float*)d_in[6];
    const float* Wv = (const float*)d_in[7];
    const float* bv = (const float*)d_in[8];
    const float* Wo = (const float*)d_in[9];
    const float* bo = (const float*)d_in[10];
    const float* temperature = (const float*)d_in[11];
    const int* wsize = (const int*)d_in[12];
    const int* gnum  = (const int*)d_in[13];
    float* out = (float*)d_out;

    int E = in_sizes[4];                 // 512
    int B = B_CONST;
    int T = in_sizes[0] / (B * E);       // 2048
    int S = in_sizes[1] / (B * E);       // 2048
    int M = B * T;                       // 4096
    int hd = E / H_NUM;

    float *qb, *kb, *vb, *aob;
    cudaGetSymbolAddress((void**)&qb,  g_q);
    cudaGetSymbolAddress((void**)&kb,  g_k);
    cudaGetSymbolAddress((void**)&vb,  g_v);
    cudaGetSymbolAddress((void**)&aob, g_ao);

    // global-token column flags
    gflags_kernel<<<(S + 255) / 256, 256>>>(S, gnum);

    dim3 ggrid(E / GBN, M / GBM);
    float scaling = 1.0f / sqrtf((float)hd);
    // q projection with hd^-0.5 * temperature folded in
    gemm_bias_kernel<<<ggrid, 256>>>(query, Wq, bq, qb, M, E, E, scaling, temperature);
    gemm_bias_kernel<<<ggrid, 256>>>(key_,  Wk, bk, kb, M, E, E, 1.0f, nullptr);
    gemm_bias_kernel<<<ggrid, 256>>>(value, Wv, bv, vb, M, E, E, 1.0f, nullptr);

    cudaFuncSetAttribute(sparse_attn_kernel,
                         cudaFuncAttributeMaxDynamicSharedMemorySize, ATT_SMEM);
    sparse_attn_kernel<<<dim3(T / AT_BM, H_NUM, B), 128, ATT_SMEM>>>(T, S, E, wsize, gnum);

    gemm_bias_kernel<<<ggrid, 256>>>(aob, Wo, bo, out, M, E, E, 1.0f, nullptr);
}

// round 4
// speedup vs baseline: 4.0672x; 2.5056x over previous
#include <cuda_runtime.h>
#include <math.h>
#include <cstdint>

#define B_CONST 2
#define H_NUM   16
#define HD      32

// ---------------- device scratch ----------------
__device__ float g_q [2*2048*512];
__device__ float g_k [2*2048*512];
__device__ float g_v [2*2048*512];
__device__ float g_ao[2*2048*512];
__device__ unsigned char g_gflag[4096];
__device__ int g_gcols[64];
__device__ int g_gcount;

// ---------------- global-token column flags / list ----------------
__global__ void gflags_kernel(int S, const int* __restrict__ Gptr) {
    int j = blockIdx.x * blockDim.x + threadIdx.x;
    if (j >= S) return;
    int G = *Gptr;
    unsigned char f = 0;
    if (G > 0) {
        int stride = S / (G + 1);
        if (G == 1) {
            if (j == stride) f = 1;
        } else {
            double stp = (double)(S - 2 * stride) / (double)(G - 1);
            for (int t = 0; t < G; t++) {
                long long gi = (t == G - 1)
                    ? (long long)(S - stride)
                    : (long long)((double)t * stp + (double)stride);
                if ((long long)j == gi) f = 1;
            }
        }
    }
    g_gflag[j] = f;
}

__global__ void glist_kernel(int S, const int* __restrict__ Gptr) {
    if (threadIdx.x != 0 || blockIdx.x != 0) return;
    int G = *Gptr;
    int n = 0;
    if (G > 0) {
        int stride = S / (G + 1);
        if (G == 1) {
            g_gcols[n++] = stride;
        } else {
            double stp = (double)(S - 2 * stride) / (double)(G - 1);
            for (int t = 0; t < G && n < 64; t++) {
                long long gi = (t == G - 1)
                    ? (long long)(S - stride)
                    : (long long)((double)t * stp + (double)stride);
                bool dup = false;
                for (int u = 0; u < n; u++) if (g_gcols[u] == (int)gi) dup = true;
                if (!dup) g_gcols[n++] = (int)gi;
            }
        }
    }
    g_gcount = n;
}

// ---------------- TF32 mma.sync GEMM core: C = (A @ W^T + bias) * alpha -----
// A: [M,K] row-major fp32, W: [N,K] row-major fp32, C: [M,N] row-major.
#define BMG 128
#define BNG 128
#define BKG 32
#define SSTR 36                    // smem row stride (floats) — conflict-free
#define GEMM_SMEM (2 * (BMG + BNG) * SSTR * 4)   // 73728 bytes

__device__ __forceinline__ uint32_t f2tf32(float x) {
    uint32_t r;
    asm("cvt.rna.tf32.f32 %0, %1;" : "=r"(r) : "f"(x));
    return r;
}

__device__ __forceinline__ void mma_tf32(float* c, const uint32_t* a, const uint32_t* b) {
    asm volatile(
        "mma.sync.aligned.m16n8k8.row.col.f32.tf32.tf32.f32 "
        "{%0,%1,%2,%3}, {%4,%5,%6,%7}, {%8,%9}, {%0,%1,%2,%3};"
        : "+f"(c[0]), "+f"(c[1]), "+f"(c[2]), "+f"(c[3])
        : "r"(a[0]), "r"(a[1]), "r"(a[2]), "r"(a[3]), "r"(b[0]), "r"(b[1]));
}

__device__ void gemm_core(const float* __restrict__ A, const float* __restrict__ W,
                          const float* __restrict__ bias, float* __restrict__ C,
                          int M, int N, int K, float alpha, float* sm) {
    float* As = sm;                         // 2 bufs of [BMG][SSTR]
    float* Bs = sm + 2 * BMG * SSTR;        // 2 bufs of [BNG][SSTR]

    int tid = threadIdx.x;
    int warp = tid >> 5, lane = tid & 31;
    int warp_m = warp >> 2;                 // 0..1
    int warp_n = warp & 3;                  // 0..3
    int gr = lane >> 2, gc = lane & 3;

    int bm = blockIdx.y * BMG;
    int bn = blockIdx.x * BNG;

    int lrow = tid >> 3;                    // 0..31
    int lc4  = (tid & 7) * 4;               // 0..28

    const float* Ap = A + (size_t)(bm + lrow) * K + lc4;
    const float* Wp = W + (size_t)(bn + lrow) * K + lc4;

    float c[4][4][4];
#pragma unroll
    for (int t = 0; t < 4; t++)
#pragma unroll
        for (int u = 0; u < 4; u++)
#pragma unroll
            for (int e = 0; e < 4; e++) c[t][u][e] = 0.f;

    float4 areg[4], breg[4];
    int nch = K / BKG;

    // prologue: chunk 0
#pragma unroll
    for (int it = 0; it < 4; it++) {
        areg[it] = *(const float4*)(Ap + (size_t)it * 32 * K);
        breg[it] = *(const float4*)(Wp + (size_t)it * 32 * K);
    }
#pragma unroll
    for (int it = 0; it < 4; it++) {
        float* da = As + (lrow + it * 32) * SSTR + lc4;
        float* db = Bs + (lrow + it * 32) * SSTR + lc4;
        ((uint32_t*)da)[0] = f2tf32(areg[it].x); ((uint32_t*)da)[1] = f2tf32(areg[it].y);
        ((uint32_t*)da)[2] = f2tf32(areg[it].z); ((uint32_t*)da)[3] = f2tf32(areg[it].w);
        ((uint32_t*)db)[0] = f2tf32(breg[it].x); ((uint32_t*)db)[1] = f2tf32(breg[it].y);
        ((uint32_t*)db)[2] = f2tf32(breg[it].z); ((uint32_t*)db)[3] = f2tf32(breg[it].w);
    }
    __syncthreads();

    for (int ch = 0; ch < nch; ch++) {
        int buf = ch & 1;
        if (ch + 1 < nch) {
            int k0n = (ch + 1) * BKG;
#pragma unroll
            for (int it = 0; it < 4; it++) {
                areg[it] = *(const float4*)(Ap + (size_t)it * 32 * K + k0n);
                breg[it] = *(const float4*)(Wp + (size_t)it * 32 * K + k0n);
            }
        }
        // compute on buf
        const uint32_t* as = (const uint32_t*)(As + buf * BMG * SSTR + warp_m * 64 * SSTR);
        const uint32_t* bs = (const uint32_t*)(Bs + buf * BNG * SSTR + warp_n * 32 * SSTR);
#pragma unroll
        for (int ks = 0; ks < 4; ks++) {
            int k0 = ks * 8;
            uint32_t af[4][4], bf[4][2];
#pragma unroll
            for (int t = 0; t < 4; t++) {
                int row = t * 16 + gr;
                af[t][0] = as[row * SSTR + k0 + gc];
                af[t][1] = as[(row + 8) * SSTR + k0 + gc];
                af[t][2] = as[row * SSTR + k0 + gc + 4];
                af[t][3] = as[(row + 8) * SSTR + k0 + gc + 4];
            }
#pragma unroll
            for (int u = 0; u < 4; u++) {
                int col = u * 8 + gr;
                bf[u][0] = bs[col * SSTR + k0 + gc];
                bf[u][1] = bs[col * SSTR + k0 + gc + 4];
            }
#pragma unroll
            for (int t = 0; t < 4; t++)
#pragma unroll
                for (int u = 0; u < 4; u++)
                    mma_tf32(c[t][u], af[t], bf[u]);
        }
        __syncthreads();
        if (ch + 1 < nch) {
            int nbuf = (ch + 1) & 1;
#pragma unroll
            for (int it = 0; it < 4; it++) {
                float* da = As + nbuf * BMG * SSTR + (lrow + it * 32) * SSTR + lc4;
                float* db = Bs + nbuf * BNG * SSTR + (lrow + it * 32) * SSTR + lc4;
                ((uint32_t*)da)[0] = f2tf32(areg[it].x); ((uint32_t*)da)[1] = f2tf32(areg[it].y);
                ((uint32_t*)da)[2] = f2tf32(areg[it].z); ((uint32_t*)da)[3] = f2tf32(areg[it].w);
                ((uint32_t*)db)[0] = f2tf32(breg[it].x); ((uint32_t*)db)[1] = f2tf32(breg[it].y);
                ((uint32_t*)db)[2] = f2tf32(breg[it].z); ((uint32_t*)db)[3] = f2tf32(breg[it].w);
            }
            __syncthreads();
        }
    }

    // epilogue
#pragma unroll
    for (int t = 0; t < 4; t++) {
        int row = bm + warp_m * 64 + t * 16 + gr;
#pragma unroll
        for (int u = 0; u < 4; u++) {
            int col = bn + warp_n * 32 + u * 8 + 2 * gc;
            float2 bb = *(const float2*)(bias + col);
            float2 o0, o1;
            o0.x = (c[t][u][0] + bb.x) * alpha;
            o0.y = (c[t][u][1] + bb.y) * alpha;
            o1.x = (c[t][u][2] + bb.x) * alpha;
            o1.y = (c[t][u][3] + bb.y) * alpha;
            *(float2*)(C + (size_t)row * N + col) = o0;
            *(float2*)(C + (size_t)(row + 8) * N + col) = o1;
        }
    }
}

// fused Q/K/V projection: blockIdx.z selects which projection
__global__ __launch_bounds__(256)
void qkv_gemm_kernel(const float* q_in, const float* k_in, const float* v_in,
                     const float* Wq, const float* Wk, const float* Wv,
                     const float* bq, const float* bk, const float* bv,
                     float* qo, float* ko, float* vo,
                     int M, int N, int K, float scaling,
                     const float* __restrict__ temp_ptr) {
    extern __shared__ float smg[];
    int z = blockIdx.z;
    const float* A; const float* W; const float* bias; float* C; float alpha;
    if (z == 0)      { A = q_in; W = Wq; bias = bq; C = qo; alpha = scaling * (*temp_ptr); }
    else if (z == 1) { A = k_in; W = Wk; bias = bk; C = ko; alpha = 1.0f; }
    else             { A = v_in; W = Wv; bias = bv; C = vo; alpha = 1.0f; }
    gemm_core(A, W, bias, C, M, N, K, alpha, smg);
}

__global__ __launch_bounds__(256)
void oproj_gemm_kernel(const float* __restrict__ A, const float* __restrict__ W,
                       const float* __restrict__ bias, float* __restrict__ C,
                       int M, int N, int K) {
    extern __shared__ float smg[];
    gemm_core(A, W, bias, C, M, N, K, 1.0f, smg);
}

// ---------------- sparse flash attention (exact contiguous ranges) ----------
// Mask per row i == [rlo_i, rhi_i) union {global cols}  (window+diag subsumed)
#define AT_BM 128
#define AT_BN 64
#define KS_STR 36

__global__ __launch_bounds__(128)
void sparse_attn_kernel(int T, int S, int E, const int* __restrict__ Wptr) {
    extern __shared__ float sm[];
    float* Ks = sm;                              // [AT_BN][KS_STR]
    float* Vs = sm + AT_BN * KS_STR;             // [AT_BN][KS_STR]
    float* Ss = Vs + AT_BN * KS_STR;             // [AT_BN][AT_BM] transposed
    unsigned char* Fl = (unsigned char*)(Ss + AT_BN * AT_BM);

    int b = blockIdx.z, h = blockIdx.y;
    int i0 = blockIdx.x * AT_BM;
    int t = threadIdx.x;
    int i = i0 + t;

    const float* qrow = g_q + ((size_t)(b * T + i)) * E + h * HD;
    float qreg[HD];
#pragma unroll
    for (int d4 = 0; d4 < HD / 4; d4++) {
        float4 v = *(const float4*)(qrow + d4 * 4);
        qreg[d4 * 4 + 0] = v.x; qreg[d4 * 4 + 1] = v.y;
        qreg[d4 * 4 + 2] = v.z; qreg[d4 * 4 + 3] = v.w;
    }

    float mrow = -INFINITY, l = 0.f;
    float acc[HD];
#pragma unroll
    for (int d = 0; d < HD; d++) acc[d] = 0.f;

    int Wl = *Wptr;
    int ov = Wl / 4, step = Wl - ov;

    // row contiguous range (block-window union; subsumes sliding window + diag)
    int klo = (i >= Wl) ? (i - Wl) / step + 1 : 0;
    int khi = i / step;
    int rlo = max(0, klo * step - ov);
    int rhi = min(S, khi * step + Wl + ov);

    // CTA union range
    int cklo = (i0 >= Wl) ? (i0 - Wl) / step + 1 : 0;
    int ckhi = (i0 + AT_BM - 1) / step;
    int c_lo = max(0, cklo * step - ov);
    int c_hi = min(S, ckhi * step + Wl + ov);

    const float* kbase = g_k + (size_t)b * S * E + h * HD;
    const float* vbase = g_v + (size_t)b * S * E + h * HD;

    int ldrow = t >> 1, ldhalf = (t & 1) * 16;

    for (int j0 = c_lo & ~(AT_BN - 1); j0 < c_hi; j0 += AT_BN) {
        {
            const float* kp = kbase + (size_t)(j0 + ldrow) * E + ldhalf;
            const float* vp = vbase + (size_t)(j0 + ldrow) * E + ldhalf;
#pragma unroll
            for (int c = 0; c < 16; c += 4) {
                *(float4*)&Ks[ldrow * KS_STR + ldhalf + c] = *(const float4*)(kp + c);
                *(float4*)&Vs[ldrow * KS_STR + ldhalf + c] = *(const float4*)(vp + c);
            }
            if (t < AT_BN) Fl[t] = g_gflag[j0 + t];
        }
        __syncthreads();

        int jlo = max(rlo, j0) - j0;
        int jhi = min(rhi, j0 + AT_BN) - j0;
        float tmax = -INFINITY;
        for (int jj = jlo; jj < jhi; jj++) {
            float s = -INFINITY;
            if (!Fl[jj]) {       // globals handled in gather pass (avoid double count)
                const float4* kr = (const float4*)&Ks[jj * KS_STR];
                float s0 = 0.f, s1 = 0.f, s2 = 0.f, s3 = 0.f;
#pragma unroll
                for (int d4 = 0; d4 < 8; d4++) {
                    float4 kk = kr[d4];
                    s0 += qreg[d4 * 4 + 0] * kk.x;
                    s1 += qreg[d4 * 4 + 1] * kk.y;
                    s2 += qreg[d4 * 4 + 2] * kk.z;
                    s3 += qreg[d4 * 4 + 3] * kk.w;
                }
                s = (s0 + s1) + (s2 + s3);
                tmax = fmaxf(tmax, s);
            }
            Ss[jj * AT_BM + t] = s;
        }

        if (tmax > -INFINITY) {
            float mnew = fmaxf(mrow, tmax);
            float cscale = __expf(mrow - mnew);
            mrow = mnew;
            l *= cscale;
#pragma unroll
            for (int d = 0; d < HD; d++) acc[d] *= cscale;
            for (int jj = jlo; jj < jhi; jj++) {
                float p = __expf(Ss[jj * AT_BM + t] - mnew);
                l += p;
                const float4* vr = (const float4*)&Vs[jj * KS_STR];
#pragma unroll
                for (int d4 = 0; d4 < 8; d4++) {
                    float4 vv = vr[d4];
                    acc[d4 * 4 + 0] += p * vv.x;
                    acc[d4 * 4 + 1] += p * vv.y;
                    acc[d4 * 4 + 2] += p * vv.z;
                    acc[d4 * 4 + 3] += p * vv.w;
                }
            }
        }
        __syncthreads();
    }

    // gather pass: all global columns (every row attends to all of them)
    int ng = g_gcount;
    if (ng > 0) {
        for (int idx = t; idx < ng * 2; idx += AT_BM) {
            int row = idx >> 1, half = (idx & 1) * 16;
            int j = g_gcols[row];
            const float* kp = kbase + (size_t)j * E + half;
            const float* vp = vbase + (size_t)j * E + half;
#pragma unroll
            for (int c = 0; c < 16; c += 4) {
                *(float4*)&Ks[row * KS_STR + half + c] = *(const float4*)(kp + c);
                *(float4*)&Vs[row * KS_STR + half + c] = *(const float4*)(vp + c);
            }
        }
        __syncthreads();

        float tmax = -INFINITY;
        for (int jj = 0; jj < ng; jj++) {
            const float4* kr = (const float4*)&Ks[jj * KS_STR];
            float s0 = 0.f, s1 = 0.f, s2 = 0.f, s3 = 0.f;
#pragma unroll
            for (int d4 = 0; d4 < 8; d4++) {
                float4 kk = kr[d4];
                s0 += qreg[d4 * 4 + 0] * kk.x;
                s1 += qreg[d4 * 4 + 1] * kk.y;
                s2 += qreg[d4 * 4 + 2] * kk.z;
                s3 += qreg[d4 * 4 + 3] * kk.w;
            }
            float s = (s0 + s1) + (s2 + s3);
            tmax = fmaxf(tmax, s);
            Ss[jj * AT_BM + t] = s;
        }
        float mnew = fmaxf(mrow, tmax);
        float cscale = __expf(mrow - mnew);
        mrow = mnew;
        l *= cscale;
#pragma unroll
        for (int d = 0; d < HD; d++) acc[d] *= cscale;
        for (int jj = 0; jj < ng; jj++) {
            float p = __expf(Ss[jj * AT_BM + t] - mnew);
            l += p;
            const float4* vr = (const float4*)&Vs[jj * KS_STR];
#pragma unroll
            for (int d4 = 0; d4 < 8; d4++) {
                float4 vv = vr[d4];
                acc[d4 * 4 + 0] += p * vv.x;
                acc[d4 * 4 + 1] += p * vv.y;
                acc[d4 * 4 + 2] += p * vv.z;
                acc[d4 * 4 + 3] += p * vv.w;
            }
        }
    }

    float inv = 1.0f / l;
    float* orow = g_ao + ((size_t)(b * T + i)) * E + h * HD;
#pragma unroll
    for (int d4 = 0; d4 < 8; d4++) {
        float4 o;
        o.x = acc[d4 * 4 + 0] * inv;
        o.y = acc[d4 * 4 + 1] * inv;
        o.z = acc[d4 * 4 + 2] * inv;
        o.w = acc[d4 * 4 + 3] * inv;
        *(float4*)(orow + d4 * 4) = o;
    }
}

#define ATT_SMEM (AT_BN * KS_STR * 4 * 2 + AT_BN * AT_BM * 4 + AT_BN + 64)

// ---------------- launch -----------------------------------------------------
extern "C" void kernel_launch(void* const* d_in, const int* in_sizes, int n_in,
                              void* d_out, int out_size) {
    const float* query = (const float*)d_in[0];
    const float* key_  = (const float*)d_in[1];
    const float* value = (const float*)d_in[2];
    const float* Wq = (const float*)d_in[3];
    const float* bq = (const float*)d_in[4];
    const float* Wk = (const float*)d_in[5];
    const float* bk = (const float*)d_in[6];
    const float* Wv = (const float*)d_in[7];
    const float* bv = (const float*)d_in[8];
    const float* Wo = (const float*)d_in[9];
    const float* bo = (const float*)d_in[10];
    const float* temperature = (const float*)d_in[11];
    const int* wsize = (const int*)d_in[12];
    const int* gnum  = (const int*)d_in[13];
    float* out = (float*)d_out;

    int E = in_sizes[4];                 // 512
    int B = B_CONST;
    int T = in_sizes[0] / (B * E);       // 2048
    int S = in_sizes[1] / (B * E);       // 2048
    int M = B * T;                       // 4096
    int hd = E / H_NUM;

    float *qb, *kb, *vb, *aob;
    cudaGetSymbolAddress((void**)&qb,  g_q);
    cudaGetSymbolAddress((void**)&kb,  g_k);
    cudaGetSymbolAddress((void**)&vb,  g_v);
    cudaGetSymbolAddress((void**)&aob, g_ao);

    gflags_kernel<<<(S + 255) / 256, 256>>>(S, gnum);
    glist_kernel<<<1, 32>>>(S, gnum);

    cudaFuncSetAttribute(qkv_gemm_kernel,
                         cudaFuncAttributeMaxDynamicSharedMemorySize, GEMM_SMEM);
    cudaFuncSetAttribute(oproj_gemm_kernel,
                         cudaFuncAttributeMaxDynamicSharedMemorySize, GEMM_SMEM);

    float scaling = 1.0f / sqrtf((float)hd);
    dim3 qkv_grid(E / BNG, M / BMG, 3);        // (4, 32, 3)
    qkv_gemm_kernel<<<qkv_grid, 256, GEMM_SMEM>>>(
        query, key_, value, Wq, Wk, Wv, bq, bk, bv,
        qb, kb, vb, M, E, E, scaling, temperature);

    cudaFuncSetAttribute(sparse_attn_kernel,
                         cudaFuncAttributeMaxDynamicSharedMemorySize, ATT_SMEM);
    sparse_attn_kernel<<<dim3(T / AT_BM, H_NUM, B), 128, ATT_SMEM>>>(T, S, E, wsize);

    dim3 ogrid(E / BNG, M / BMG);
    oproj_gemm_kernel<<<ogrid, 256, GEMM_SMEM>>>(aob, Wo, bo, out, M, E, E);
}

// round 5
// speedup vs baseline: 4.4925x; 1.1046x over previous
#include <cuda_runtime.h>
#include <math.h>
#include <cstdint>

#define B_CONST 2
#define H_NUM   16
#define HD      32

// ---------------- device scratch ----------------
__device__ float g_q [2*2048*512];
__device__ float g_k [2*2048*512];
__device__ float g_v [2*2048*512];
__device__ float g_ao[2*2048*512];
__device__ int g_gcols[64];
__device__ int g_gcount;

// ---------------- global-token column list ----------------
__global__ void glist_kernel(int S, const int* __restrict__ Gptr) {
    if (threadIdx.x != 0 || blockIdx.x != 0) return;
    int G = *Gptr;
    int n = 0;
    if (G > 0) {
        int stride = S / (G + 1);
        if (G == 1) {
            g_gcols[n++] = stride;
        } else {
            double stp = (double)(S - 2 * stride) / (double)(G - 1);
            for (int t = 0; t < G && n < 64; t++) {
                long long gi = (t == G - 1)
                    ? (long long)(S - stride)
                    : (long long)((double)t * stp + (double)stride);
                bool dup = false;
                for (int u = 0; u < n; u++) if (g_gcols[u] == (int)gi) dup = true;
                if (!dup) g_gcols[n++] = (int)gi;
            }
        }
    }
    g_gcount = n;
}

// ---------------- TF32 mma.sync GEMM core: C = (A @ W^T + bias) * alpha -----
#define BMG 128
#define BNG 128
#define BKG 32
#define SSTR 36
#define GEMM_SMEM (2 * (BMG + BNG) * SSTR * 4)   // 73728 bytes

__device__ __forceinline__ uint32_t f2tf32(float x) {
    uint32_t r;
    asm("cvt.rna.tf32.f32 %0, %1;" : "=r"(r) : "f"(x));
    return r;
}

__device__ __forceinline__ void mma_tf32(float* c, const uint32_t* a, const uint32_t* b) {
    asm volatile(
        "mma.sync.aligned.m16n8k8.row.col.f32.tf32.tf32.f32 "
        "{%0,%1,%2,%3}, {%4,%5,%6,%7}, {%8,%9}, {%0,%1,%2,%3};"
        : "+f"(c[0]), "+f"(c[1]), "+f"(c[2]), "+f"(c[3])
        : "r"(a[0]), "r"(a[1]), "r"(a[2]), "r"(a[3]), "r"(b[0]), "r"(b[1]));
}

__device__ void gemm_core(const float* __restrict__ A, const float* __restrict__ W,
                          const float* __restrict__ bias, float* __restrict__ C,
                          int M, int N, int K, float alpha, float* sm) {
    float* As = sm;
    float* Bs = sm + 2 * BMG * SSTR;

    int tid = threadIdx.x;
    int warp = tid >> 5, lane = tid & 31;
    int warp_m = warp >> 2;
    int warp_n = warp & 3;
    int gr = lane >> 2, gc = lane & 3;

    int bm = blockIdx.y * BMG;
    int bn = blockIdx.x * BNG;

    int lrow = tid >> 3;
    int lc4  = (tid & 7) * 4;

    const float* Ap = A + (size_t)(bm + lrow) * K + lc4;
    const float* Wp = W + (size_t)(bn + lrow) * K + lc4;

    float c[4][4][4];
#pragma unroll
    for (int t = 0; t < 4; t++)
#pragma unroll
        for (int u = 0; u < 4; u++)
#pragma unroll
            for (int e = 0; e < 4; e++) c[t][u][e] = 0.f;

    float4 areg[4], breg[4];
    int nch = K / BKG;

#pragma unroll
    for (int it = 0; it < 4; it++) {
        areg[it] = *(const float4*)(Ap + (size_t)it * 32 * K);
        breg[it] = *(const float4*)(Wp + (size_t)it * 32 * K);
    }
#pragma unroll
    for (int it = 0; it < 4; it++) {
        float* da = As + (lrow + it * 32) * SSTR + lc4;
        float* db = Bs + (lrow + it * 32) * SSTR + lc4;
        ((uint32_t*)da)[0] = f2tf32(areg[it].x); ((uint32_t*)da)[1] = f2tf32(areg[it].y);
        ((uint32_t*)da)[2] = f2tf32(areg[it].z); ((uint32_t*)da)[3] = f2tf32(areg[it].w);
        ((uint32_t*)db)[0] = f2tf32(breg[it].x); ((uint32_t*)db)[1] = f2tf32(breg[it].y);
        ((uint32_t*)db)[2] = f2tf32(breg[it].z); ((uint32_t*)db)[3] = f2tf32(breg[it].w);
    }
    __syncthreads();

    for (int ch = 0; ch < nch; ch++) {
        int buf = ch & 1;
        if (ch + 1 < nch) {
            int k0n = (ch + 1) * BKG;
#pragma unroll
            for (int it = 0; it < 4; it++) {
                areg[it] = *(const float4*)(Ap + (size_t)it * 32 * K + k0n);
                breg[it] = *(const float4*)(Wp + (size_t)it * 32 * K + k0n);
            }
        }
        const uint32_t* as = (const uint32_t*)(As + buf * BMG * SSTR + warp_m * 64 * SSTR);
        const uint32_t* bs = (const uint32_t*)(Bs + buf * BNG * SSTR + warp_n * 32 * SSTR);
#pragma unroll
        for (int ks = 0; ks < 4; ks++) {
            int k0 = ks * 8;
            uint32_t af[4][4], bf[4][2];
#pragma unroll
            for (int t = 0; t < 4; t++) {
                int row = t * 16 + gr;
                af[t][0] = as[row * SSTR + k0 + gc];
                af[t][1] = as[(row + 8) * SSTR + k0 + gc];
                af[t][2] = as[row * SSTR + k0 + gc + 4];
                af[t][3] = as[(row + 8) * SSTR + k0 + gc + 4];
            }
#pragma unroll
            for (int u = 0; u < 4; u++) {
                int col = u * 8 + gr;
                bf[u][0] = bs[col * SSTR + k0 + gc];
                bf[u][1] = bs[col * SSTR + k0 + gc + 4];
            }
#pragma unroll
            for (int t = 0; t < 4; t++)
#pragma unroll
                for (int u = 0; u < 4; u++)
                    mma_tf32(c[t][u], af[t], bf[u]);
        }
        __syncthreads();
        if (ch + 1 < nch) {
            int nbuf = (ch + 1) & 1;
#pragma unroll
            for (int it = 0; it < 4; it++) {
                float* da = As + nbuf * BMG * SSTR + (lrow + it * 32) * SSTR + lc4;
                float* db = Bs + nbuf * BNG * SSTR + (lrow + it * 32) * SSTR + lc4;
                ((uint32_t*)da)[0] = f2tf32(areg[it].x); ((uint32_t*)da)[1] = f2tf32(areg[it].y);
                ((uint32_t*)da)[2] = f2tf32(areg[it].z); ((uint32_t*)da)[3] = f2tf32(areg[it].w);
                ((uint32_t*)db)[0] = f2tf32(breg[it].x); ((uint32_t*)db)[1] = f2tf32(breg[it].y);
                ((uint32_t*)db)[2] = f2tf32(breg[it].z); ((uint32_t*)db)[3] = f2tf32(breg[it].w);
            }
            __syncthreads();
        }
    }

#pragma unroll
    for (int t = 0; t < 4; t++) {
        int row = bm + warp_m * 64 + t * 16 + gr;
#pragma unroll
        for (int u = 0; u < 4; u++) {
            int col = bn + warp_n * 32 + u * 8 + 2 * gc;
            float2 bb = *(const float2*)(bias + col);
            float2 o0, o1;
            o0.x = (c[t][u][0] + bb.x) * alpha;
            o0.y = (c[t][u][1] + bb.y) * alpha;
            o1.x = (c[t][u][2] + bb.x) * alpha;
            o1.y = (c[t][u][3] + bb.y) * alpha;
            *(float2*)(C + (size_t)row * N + col) = o0;
            *(float2*)(C + (size_t)(row + 8) * N + col) = o1;
        }
    }
}

__global__ __launch_bounds__(256)
void qkv_gemm_kernel(const float* q_in, const float* k_in, const float* v_in,
                     const float* Wq, const float* Wk, const float* Wv,
                     const float* bq, const float* bk, const float* bv,
                     float* qo, float* ko, float* vo,
                     int M, int N, int K, float scaling,
                     const float* __restrict__ temp_ptr) {
    extern __shared__ float smg[];
    int z = blockIdx.z;
    const float* A; const float* W; const float* bias; float* C; float alpha;
    if (z == 0)      { A = q_in; W = Wq; bias = bq; C = qo; alpha = scaling * (*temp_ptr); }
    else if (z == 1) { A = k_in; W = Wk; bias = bk; C = ko; alpha = 1.0f; }
    else             { A = v_in; W = Wv; bias = bv; C = vo; alpha = 1.0f; }
    gemm_core(A, W, bias, C, M, N, K, alpha, smg);
}

__global__ __launch_bounds__(256)
void oproj_gemm_kernel(const float* __restrict__ A, const float* __restrict__ W,
                       const float* __restrict__ bias, float* __restrict__ C,
                       int M, int N, int K) {
    extern __shared__ float smg[];
    gemm_core(A, W, bias, C, M, N, K, 1.0f, smg);
}

// ---------------- sparse flash attention v3 --------------------------------
// Row mask == [rlo_i, rhi_i) union {global cols}; main loop covers the range
// unconditionally, gather pass adds only globals OUTSIDE [rlo, rhi).
#define AT_BM 128
#define AT_BN 64
#define KS_STR 36
#define ATT_SMEM (2 * AT_BN * KS_STR * 4 + 64)

__global__ __launch_bounds__(128)
void sparse_attn_kernel(int T, int S, int E, const int* __restrict__ Wptr) {
    extern __shared__ float sm[];
    float* Ks = sm;                      // [AT_BN][KS_STR]
    float* Vs = sm + AT_BN * KS_STR;     // [AT_BN][KS_STR]

    int b = blockIdx.z, h = blockIdx.y;
    int i0 = blockIdx.x * AT_BM;
    int t = threadIdx.x;
    int i = i0 + t;

    const float* qrow = g_q + ((size_t)(b * T + i)) * E + h * HD;
    float qreg[HD];
#pragma unroll
    for (int d4 = 0; d4 < HD / 4; d4++) {
        float4 v = *(const float4*)(qrow + d4 * 4);
        qreg[d4 * 4 + 0] = v.x; qreg[d4 * 4 + 1] = v.y;
        qreg[d4 * 4 + 2] = v.z; qreg[d4 * 4 + 3] = v.w;
    }

    float mrow = -INFINITY, l = 0.f;
    float acc[HD];
#pragma unroll
    for (int d = 0; d < HD; d++) acc[d] = 0.f;

    int Wl = *Wptr;
    int ov = Wl / 4, step = Wl - ov;

    int klo = (i >= Wl) ? (i - Wl) / step + 1 : 0;
    int khi = i / step;
    int rlo = max(0, klo * step - ov);
    int rhi = min(S, khi * step + Wl + ov);

    int cklo = (i0 >= Wl) ? (i0 - Wl) / step + 1 : 0;
    int ckhi = (i0 + AT_BM - 1) / step;
    int c_lo = max(0, cklo * step - ov);
    int c_hi = min(S, ckhi * step + Wl + ov);

    const float* kbase = g_k + (size_t)b * S * E + h * HD;
    const float* vbase = g_v + (size_t)b * S * E + h * HD;

    int ldrow = t >> 1, ldhalf = (t & 1) * 16;

    for (int j0 = c_lo & ~(AT_BN - 1); j0 < c_hi; j0 += AT_BN) {
        {
            const float* kp = kbase + (size_t)(j0 + ldrow) * E + ldhalf;
            const float* vp = vbase + (size_t)(j0 + ldrow) * E + ldhalf;
#pragma unroll
            for (int c = 0; c < 16; c += 4) {
                *(float4*)&Ks[ldrow * KS_STR + ldhalf + c] = *(const float4*)(kp + c);
                *(float4*)&Vs[ldrow * KS_STR + ldhalf + c] = *(const float4*)(vp + c);
            }
        }
        __syncthreads();

        int jlo = max(rlo, j0) - j0;
        int jhi = min(rhi, j0 + AT_BN) - j0;

        for (int jc = jlo; jc < jhi; jc += 8) {
            float s[8];
            float cmax = -INFINITY;
#pragma unroll
            for (int c = 0; c < 8; c++) {
                s[c] = -INFINITY;
                if (jc + c < jhi) {
                    const float4* kr = (const float4*)&Ks[(jc + c) * KS_STR];
                    float s0 = 0.f, s1 = 0.f, s2 = 0.f, s3 = 0.f;
#pragma unroll
                    for (int d4 = 0; d4 < 8; d4++) {
                        float4 kk = kr[d4];
                        s0 += qreg[d4 * 4 + 0] * kk.x;
                        s1 += qreg[d4 * 4 + 1] * kk.y;
                        s2 += qreg[d4 * 4 + 2] * kk.z;
                        s3 += qreg[d4 * 4 + 3] * kk.w;
                    }
                    s[c] = (s0 + s1) + (s2 + s3);
                    cmax = fmaxf(cmax, s[c]);
                }
            }
            float mnew = fmaxf(mrow, cmax);
            float cscale = __expf(mrow - mnew);   // mrow>-inf here (diag in range)
            mrow = mnew;
            l *= cscale;
#pragma unroll
            for (int d = 0; d < HD; d++) acc[d] *= cscale;
#pragma unroll
            for (int c = 0; c < 8; c++) {
                float p = __expf(s[c] - mnew);    // -inf lanes -> 0
                l += p;
                const float4* vr = (const float4*)&Vs[(jc + c) * KS_STR];
#pragma unroll
                for (int d4 = 0; d4 < 8; d4++) {
                    float4 vv = vr[d4];
                    acc[d4 * 4 + 0] += p * vv.x;
                    acc[d4 * 4 + 1] += p * vv.y;
                    acc[d4 * 4 + 2] += p * vv.z;
                    acc[d4 * 4 + 3] += p * vv.w;
                }
            }
        }
        __syncthreads();
    }

    // gather pass: only global columns OUTSIDE this row's [rlo, rhi)
    int ng = g_gcount;
    if (ng > 0) {
        for (int idx = t; idx < ng * 2; idx += AT_BM) {
            int row = idx >> 1, half = (idx & 1) * 16;
            int j = g_gcols[row];
            const float* kp = kbase + (size_t)j * E + half;
            const float* vp = vbase + (size_t)j * E + half;
#pragma unroll
            for (int c = 0; c < 16; c += 4) {
                *(float4*)&Ks[row * KS_STR + half + c] = *(const float4*)(kp + c);
                *(float4*)&Vs[row * KS_STR + half + c] = *(const float4*)(vp + c);
            }
        }
        __syncthreads();

        for (int jc = 0; jc < ng; jc += 8) {
            float s[8];
            float cmax = -INFINITY;
#pragma unroll
            for (int c = 0; c < 8; c++) {
                s[c] = -INFINITY;
                if (jc + c < ng) {
                    int j = g_gcols[jc + c];
                    if (j < rlo || j >= rhi) {    // skip in-range (already counted)
                        const float4* kr = (const float4*)&Ks[(jc + c) * KS_STR];
                        float s0 = 0.f, s1 = 0.f, s2 = 0.f, s3 = 0.f;
#pragma unroll
                        for (int d4 = 0; d4 < 8; d4++) {
                            float4 kk = kr[d4];
                            s0 += qreg[d4 * 4 + 0] * kk.x;
                            s1 += qreg[d4 * 4 + 1] * kk.y;
                            s2 += qreg[d4 * 4 + 2] * kk.z;
                            s3 += qreg[d4 * 4 + 3] * kk.w;
                        }
                        s[c] = (s0 + s1) + (s2 + s3);
                        cmax = fmaxf(cmax, s[c]);
                    }
                }
            }
            if (cmax > -INFINITY) {
                float mnew = fmaxf(mrow, cmax);
                float cscale = __expf(mrow - mnew);
                mrow = mnew;
                l *= cscale;
#pragma unroll
                for (int d = 0; d < HD; d++) acc[d] *= cscale;
#pragma unroll
                for (int c = 0; c < 8; c++) {
                    float p = __expf(s[c] - mnew);
                    l += p;
                    const float4* vr = (const float4*)&Vs[(jc + c) * KS_STR];
#pragma unroll
                    for (int d4 = 0; d4 < 8; d4++) {
                        float4 vv = vr[d4];
                        acc[d4 * 4 + 0] += p * vv.x;
                        acc[d4 * 4 + 1] += p * vv.y;
                        acc[d4 * 4 + 2] += p * vv.z;
                        acc[d4 * 4 + 3] += p * vv.w;
                    }
                }
            }
        }
    }

    float inv = 1.0f / l;
    float* orow = g_ao + ((size_t)(b * T + i)) * E + h * HD;
#pragma unroll
    for (int d4 = 0; d4 < 8; d4++) {
        float4 o;
        o.x = acc[d4 * 4 + 0] * inv;
        o.y = acc[d4 * 4 + 1] * inv;
        o.z = acc[d4 * 4 + 2] * inv;
        o.w = acc[d4 * 4 + 3] * inv;
        *(float4*)(orow + d4 * 4) = o;
    }
}

// ---------------- launch -----------------------------------------------------
extern "C" void kernel_launch(void* const* d_in, const int* in_sizes, int n_in,
                              void* d_out, int out_size) {
    const float* query = (const float*)d_in[0];
    const float* key_  = (const float*)d_in[1];
    const float* value = (const float*)d_in[2];
    const float* Wq = (const float*)d_in[3];
    const float* bq = (const float*)d_in[4];
    const float* Wk = (const float*)d_in[5];
    const float* bk = (const float*)d_in[6];
    const float* Wv = (const float*)d_in[7];
    const float* bv = (const float*)d_in[8];
    const float* Wo = (const float*)d_in[9];
    const float* bo = (const float*)d_in[10];
    const float* temperature = (const float*)d_in[11];
    const int* wsize = (const int*)d_in[12];
    const int* gnum  = (const int*)d_in[13];
    float* out = (float*)d_out;

    int E = in_sizes[4];                 // 512
    int B = B_CONST;
    int T = in_sizes[0] / (B * E);       // 2048
    int S = in_sizes[1] / (B * E);       // 2048
    int M = B * T;                       // 4096
    int hd = E / H_NUM;

    float *qb, *kb, *vb, *aob;
    cudaGetSymbolAddress((void**)&qb,  g_q);
    cudaGetSymbolAddress((void**)&kb,  g_k);
    cudaGetSymbolAddress((void**)&vb,  g_v);
    cudaGetSymbolAddress((void**)&aob, g_ao);

    glist_kernel<<<1, 32>>>(S, gnum);

    cudaFuncSetAttribute(qkv_gemm_kernel,
                         cudaFuncAttributeMaxDynamicSharedMemorySize, GEMM_SMEM);
    cudaFuncSetAttribute(oproj_gemm_kernel,
                         cudaFuncAttributeMaxDynamicSharedMemorySize, GEMM_SMEM);

    float scaling = 1.0f / sqrtf((float)hd);
    dim3 qkv_grid(E / BNG, M / BMG, 3);
    qkv_gemm_kernel<<<qkv_grid, 256, GEMM_SMEM>>>(
        query, key_, value, Wq, Wk, Wv, bq, bk, bv,
        qb, kb, vb, M, E, E, scaling, temperature);

    cudaFuncSetAttribute(sparse_attn_kernel,
                         cudaFuncAttributeMaxDynamicSharedMemorySize, ATT_SMEM);
    sparse_attn_kernel<<<dim3(T / AT_BM, H_NUM, B), 128, ATT_SMEM>>>(T, S, E, wsize);

    dim3 ogrid(E / BNG, M / BMG);
    oproj_gemm_kernel<<<ogrid, 256, GEMM_SMEM>>>(aob, Wo, bo, out, M, E, E);
}

// round 6
// speedup vs baseline: 4.5131x; 1.0046x over previous
#include <cuda_runtime.h>
#include <math.h>
#include <cstdint>

#define B_CONST 2
#define H_NUM   16
#define HD      32

typedef unsigned long long u64;

// ---------------- device scratch ----------------
__device__ float g_q [2*2048*512];
__device__ float g_k [2*2048*512];
__device__ float g_v [2*2048*512];
__device__ float g_ao[2*2048*512];
__device__ int g_gcols[64];
__device__ int g_gcount;

// ---------------- packed f32x2 helpers ----------------
__device__ __forceinline__ u64 pack2(float lo, float hi) {
    u64 r; asm("mov.b64 %0, {%1, %2};" : "=l"(r) : "f"(lo), "f"(hi)); return r;
}
__device__ __forceinline__ void unpack2(u64 v, float& lo, float& hi) {
    asm("mov.b64 {%0, %1}, %2;" : "=f"(lo), "=f"(hi) : "l"(v));
}
__device__ __forceinline__ u64 fma2(u64 a, u64 b, u64 c) {
    u64 d; asm("fma.rn.f32x2 %0, %1, %2, %3;" : "=l"(d) : "l"(a), "l"(b), "l"(c)); return d;
}
__device__ __forceinline__ u64 mul2(u64 a, u64 b) {
    u64 d; asm("mul.rn.f32x2 %0, %1, %2;" : "=l"(d) : "l"(a), "l"(b)); return d;
}

// ---------------- global-token column list ----------------
__global__ void glist_kernel(int S, const int* __restrict__ Gptr) {
    if (threadIdx.x != 0 || blockIdx.x != 0) return;
    int G = *Gptr;
    int n = 0;
    if (G > 0) {
        int stride = S / (G + 1);
        if (G == 1) {
            g_gcols[n++] = stride;
        } else {
            double stp = (double)(S - 2 * stride) / (double)(G - 1);
            for (int t = 0; t < G && n < 64; t++) {
                long long gi = (t == G - 1)
                    ? (long long)(S - stride)
                    : (long long)((double)t * stp + (double)stride);
                bool dup = false;
                for (int u = 0; u < n; u++) if (g_gcols[u] == (int)gi) dup = true;
                if (!dup) g_gcols[n++] = (int)gi;
            }
        }
    }
    g_gcount = n;
}

// ---------------- TF32 mma.sync GEMM: C = (A @ W^T + bias) * alpha ----------
// BNG=64: 32 acc regs/thread -> 2 CTAs/SM; grid covers all SMs.
#define BMG 128
#define BNG 64
#define BKG 32
#define SSTR 36
#define GEMM_SMEM (2 * (BMG + BNG) * SSTR * 4)   // 55296 bytes

__device__ __forceinline__ uint32_t f2tf32(float x) {
    uint32_t r;
    asm("cvt.rna.tf32.f32 %0, %1;" : "=r"(r) : "f"(x));
    return r;
}

__device__ __forceinline__ void mma_tf32(float* c, const uint32_t* a, const uint32_t* b) {
    asm volatile(
        "mma.sync.aligned.m16n8k8.row.col.f32.tf32.tf32.f32 "
        "{%0,%1,%2,%3}, {%4,%5,%6,%7}, {%8,%9}, {%0,%1,%2,%3};"
        : "+f"(c[0]), "+f"(c[1]), "+f"(c[2]), "+f"(c[3])
        : "r"(a[0]), "r"(a[1]), "r"(a[2]), "r"(a[3]), "r"(b[0]), "r"(b[1]));
}

__device__ void gemm_core(const float* __restrict__ A, const float* __restrict__ W,
                          const float* __restrict__ bias, float* __restrict__ C,
                          int M, int N, int K, float alpha, float* sm) {
    float* As = sm;                          // 2 bufs of [BMG][SSTR]
    float* Bs = sm + 2 * BMG * SSTR;         // 2 bufs of [BNG][SSTR]

    int tid = threadIdx.x;
    int warp = tid >> 5, lane = tid & 31;
    int warp_m = warp >> 2;                  // 0..1 -> 64 rows
    int warp_n = warp & 3;                   // 0..3 -> 16 cols
    int gr = lane >> 2, gc = lane & 3;

    int bm = blockIdx.y * BMG;
    int bn = blockIdx.x * BNG;

    int lrow = tid >> 3;                     // 0..31
    int lc4  = (tid & 7) * 4;

    const float* Ap = A + (size_t)(bm + lrow) * K + lc4;
    const float* Wp = W + (size_t)(bn + lrow) * K + lc4;

    float c[4][2][4];
#pragma unroll
    for (int t = 0; t < 4; t++)
#pragma unroll
        for (int u = 0; u < 2; u++)
#pragma unroll
            for (int e = 0; e < 4; e++) c[t][u][e] = 0.f;

    float4 areg[4], breg[2];
    int nch = K / BKG;

#pragma unroll
    for (int it = 0; it < 4; it++)
        areg[it] = *(const float4*)(Ap + (size_t)it * 32 * K);
#pragma unroll
    for (int it = 0; it < 2; it++)
        breg[it] = *(const float4*)(Wp + (size_t)it * 32 * K);
#pragma unroll
    for (int it = 0; it < 4; it++) {
        float* da = As + (lrow + it * 32) * SSTR + lc4;
        ((uint32_t*)da)[0] = f2tf32(areg[it].x); ((uint32_t*)da)[1] = f2tf32(areg[it].y);
        ((uint32_t*)da)[2] = f2tf32(areg[it].z); ((uint32_t*)da)[3] = f2tf32(areg[it].w);
    }
#pragma unroll
    for (int it = 0; it < 2; it++) {
        float* db = Bs + (lrow + it * 32) * SSTR + lc4;
        ((uint32_t*)db)[0] = f2tf32(breg[it].x); ((uint32_t*)db)[1] = f2tf32(breg[it].y);
        ((uint32_t*)db)[2] = f2tf32(breg[it].z); ((uint32_t*)db)[3] = f2tf32(breg[it].w);
    }
    __syncthreads();

    for (int ch = 0; ch < nch; ch++) {
        int buf = ch & 1;
        if (ch + 1 < nch) {
            int k0n = (ch + 1) * BKG;
#pragma unroll
            for (int it = 0; it < 4; it++)
                areg[it] = *(const float4*)(Ap + (size_t)it * 32 * K + k0n);
#pragma unroll
            for (int it = 0; it < 2; it++)
                breg[it] = *(const float4*)(Wp + (size_t)it * 32 * K + k0n);
        }
        const uint32_t* as = (const uint32_t*)(As + buf * BMG * SSTR + warp_m * 64 * SSTR);
        const uint32_t* bs = (const uint32_t*)(Bs + buf * BNG * SSTR + warp_n * 16 * SSTR);
#pragma unroll
        for (int ks = 0; ks < 4; ks++) {
            int k0 = ks * 8;
            uint32_t af[4][4], bf[2][2];
#pragma unroll
            for (int t = 0; t < 4; t++) {
                int row = t * 16 + gr;
                af[t][0] = as[row * SSTR + k0 + gc];
                af[t][1] = as[(row + 8) * SSTR + k0 + gc];
                af[t][2] = as[row * SSTR + k0 + gc + 4];
                af[t][3] = as[(row + 8) * SSTR + k0 + gc + 4];
            }
#pragma unroll
            for (int u = 0; u < 2; u++) {
                int col = u * 8 + gr;
                bf[u][0] = bs[col * SSTR + k0 + gc];
                bf[u][1] = bs[col * SSTR + k0 + gc + 4];
            }
#pragma unroll
            for (int t = 0; t < 4; t++)
#pragma unroll
                for (int u = 0; u < 2; u++)
                    mma_tf32(c[t][u], af[t], bf[u]);
        }
        __syncthreads();
        if (ch + 1 < nch) {
            int nbuf = (ch + 1) & 1;
#pragma unroll
            for (int it = 0; it < 4; it++) {
                float* da = As + nbuf * BMG * SSTR + (lrow + it * 32) * SSTR + lc4;
                ((uint32_t*)da)[0] = f2tf32(areg[it].x); ((uint32_t*)da)[1] = f2tf32(areg[it].y);
                ((uint32_t*)da)[2] = f2tf32(areg[it].z); ((uint32_t*)da)[3] = f2tf32(areg[it].w);
            }
#pragma unroll
            for (int it = 0; it < 2; it++) {
                float* db = Bs + nbuf * BNG * SSTR + (lrow + it * 32) * SSTR + lc4;
                ((uint32_t*)db)[0] = f2tf32(breg[it].x); ((uint32_t*)db)[1] = f2tf32(breg[it].y);
                ((uint32_t*)db)[2] = f2tf32(breg[it].z); ((uint32_t*)db)[3] = f2tf32(breg[it].w);
            }
            __syncthreads();
        }
    }

#pragma unroll
    for (int t = 0; t < 4; t++) {
        int row = bm + warp_m * 64 + t * 16 + gr;
#pragma unroll
        for (int u = 0; u < 2; u++) {
            int col = bn + warp_n * 16 + u * 8 + 2 * gc;
            float2 bb = *(const float2*)(bias + col);
            float2 o0, o1;
            o0.x = (c[t][u][0] + bb.x) * alpha;
            o0.y = (c[t][u][1] + bb.y) * alpha;
            o1.x = (c[t][u][2] + bb.x) * alpha;
            o1.y = (c[t][u][3] + bb.y) * alpha;
            *(float2*)(C + (size_t)row * N + col) = o0;
            *(float2*)(C + (size_t)(row + 8) * N + col) = o1;
        }
    }
}

__global__ __launch_bounds__(256)
void qkv_gemm_kernel(const float* q_in, const float* k_in, const float* v_in,
                     const float* Wq, const float* Wk, const float* Wv,
                     const float* bq, const float* bk, const float* bv,
                     float* qo, float* ko, float* vo,
                     int M, int N, int K, float scaling,
                     const float* __restrict__ temp_ptr) {
    extern __shared__ float smg[];
    int z = blockIdx.z;
    const float* A; const float* W; const float* bias; float* C; float alpha;
    if (z == 0)      { A = q_in; W = Wq; bias = bq; C = qo; alpha = scaling * (*temp_ptr); }
    else if (z == 1) { A = k_in; W = Wk; bias = bk; C = ko; alpha = 1.0f; }
    else             { A = v_in; W = Wv; bias = bv; C = vo; alpha = 1.0f; }
    gemm_core(A, W, bias, C, M, N, K, alpha, smg);
}

__global__ __launch_bounds__(256)
void oproj_gemm_kernel(const float* __restrict__ A, const float* __restrict__ W,
                       const float* __restrict__ bias, float* __restrict__ C,
                       int M, int N, int K) {
    extern __shared__ float smg[];
    gemm_core(A, W, bias, C, M, N, K, 1.0f, smg);
}

// ---------------- sparse flash attention v4 (packed f32x2) -----------------
#define AT_BM 128
#define AT_BN 64
#define KS_STR 36
#define ATT_SMEM (2 * AT_BN * KS_STR * 4 + 64)

__global__ __launch_bounds__(128)
void sparse_attn_kernel(int T, int S, int E, const int* __restrict__ Wptr) {
    extern __shared__ float sm[];
    float* Ks = sm;                      // [AT_BN][KS_STR]
    float* Vs = sm + AT_BN * KS_STR;     // [AT_BN][KS_STR]

    int b = blockIdx.z, h = blockIdx.y;
    int i0 = blockIdx.x * AT_BM;
    int t = threadIdx.x;
    int i = i0 + t;

    const float* qrow = g_q + ((size_t)(b * T + i)) * E + h * HD;
    u64 q2[16];
#pragma unroll
    for (int d8 = 0; d8 < 8; d8++) {
        ulonglong2 v = *(const ulonglong2*)(qrow + d8 * 4);
        q2[d8 * 2] = v.x; q2[d8 * 2 + 1] = v.y;
    }

    float mrow = -INFINITY, l = 0.f;
    u64 acc2[16];
#pragma unroll
    for (int d = 0; d < 16; d++) acc2[d] = 0ull;

    int Wl = *Wptr;
    int ov = Wl / 4, step = Wl - ov;

    int klo = (i >= Wl) ? (i - Wl) / step + 1 : 0;
    int khi = i / step;
    int rlo = max(0, klo * step - ov);
    int rhi = min(S, khi * step + Wl + ov);

    int cklo = (i0 >= Wl) ? (i0 - Wl) / step + 1 : 0;
    int ckhi = (i0 + AT_BM - 1) / step;
    int c_lo = max(0, cklo * step - ov);
    int c_hi = min(S, ckhi * step + Wl + ov);

    const float* kbase = g_k + (size_t)b * S * E + h * HD;
    const float* vbase = g_v + (size_t)b * S * E + h * HD;

    int ldrow = t >> 1, ldhalf = (t & 1) * 16;

    for (int j0 = c_lo & ~(AT_BN - 1); j0 < c_hi; j0 += AT_BN) {
        {
            const float* kp = kbase + (size_t)(j0 + ldrow) * E + ldhalf;
            const float* vp = vbase + (size_t)(j0 + ldrow) * E + ldhalf;
#pragma unroll
            for (int c = 0; c < 16; c += 4) {
                *(float4*)&Ks[ldrow * KS_STR + ldhalf + c] = *(const float4*)(kp + c);
                *(float4*)&Vs[ldrow * KS_STR + ldhalf + c] = *(const float4*)(vp + c);
            }
        }
        __syncthreads();

        int jlo = max(rlo, j0) - j0;
        int jhi = min(rhi, j0 + AT_BN) - j0;

        for (int jc = jlo; jc < jhi; jc += 8) {
            float s[8];
            float cmax = -INFINITY;
#pragma unroll
            for (int c = 0; c < 8; c++) {
                s[c] = -INFINITY;
                if (jc + c < jhi) {
                    const ulonglong2* kr = (const ulonglong2*)&Ks[(jc + c) * KS_STR];
                    u64 z0 = 0ull, z1 = 0ull;
#pragma unroll
                    for (int d8 = 0; d8 < 8; d8++) {
                        ulonglong2 kk = kr[d8];
                        z0 = fma2(q2[d8 * 2],     kk.x, z0);
                        z1 = fma2(q2[d8 * 2 + 1], kk.y, z1);
                    }
                    float a0, a1, b0, b1;
                    unpack2(z0, a0, a1);
                    unpack2(z1, b0, b1);
                    s[c] = (a0 + b0) + (a1 + b1);
                    cmax = fmaxf(cmax, s[c]);
                }
            }
            float mnew = fmaxf(mrow, cmax);
            float cscale = __expf(mrow - mnew);   // mrow>-inf here (diag in range)
            mrow = mnew;
            l *= cscale;
            u64 cs2 = pack2(cscale, cscale);
#pragma unroll
            for (int d = 0; d < 16; d++) acc2[d] = mul2(acc2[d], cs2);
#pragma unroll
            for (int c = 0; c < 8; c++) {
                float p = __expf(s[c] - mnew);    // -inf lanes -> 0
                l += p;
                u64 pp = pack2(p, p);
                const ulonglong2* vr = (const ulonglong2*)&Vs[(jc + c) * KS_STR];
#pragma unroll
                for (int d8 = 0; d8 < 8; d8++) {
                    ulonglong2 vv = vr[d8];
                    acc2[d8 * 2]     = fma2(pp, vv.x, acc2[d8 * 2]);
                    acc2[d8 * 2 + 1] = fma2(pp, vv.y, acc2[d8 * 2 + 1]);
                }
            }
        }
        __syncthreads();
    }

    // gather pass: only global columns OUTSIDE this row's [rlo, rhi)
    int ng = g_gcount;
    if (ng > 0) {
        for (int idx = t; idx < ng * 2; idx += AT_BM) {
            int row = idx >> 1, half = (idx & 1) * 16;
            int j = g_gcols[row];
            const float* kp = kbase + (size_t)j * E + half;
            const float* vp = vbase + (size_t)j * E + half;
#pragma unroll
            for (int c = 0; c < 16; c += 4) {
                *(float4*)&Ks[row * KS_STR + half + c] = *(const float4*)(kp + c);
                *(float4*)&Vs[row * KS_STR + half + c] = *(const float4*)(vp + c);
            }
        }
        __syncthreads();

        for (int jc = 0; jc < ng; jc += 8) {
            float s[8];
            float cmax = -INFINITY;
#pragma unroll
            for (int c = 0; c < 8; c++) {
                s[c] = -INFINITY;
                if (jc + c < ng) {
                    int j = g_gcols[jc + c];
                    if (j < rlo || j >= rhi) {
                        const ulonglong2* kr = (const ulonglong2*)&Ks[(jc + c) * KS_STR];
                        u64 z0 = 0ull, z1 = 0ull;
#pragma unroll
                        for (int d8 = 0; d8 < 8; d8++) {
                            ulonglong2 kk = kr[d8];
                            z0 = fma2(q2[d8 * 2],     kk.x, z0);
                            z1 = fma2(q2[d8 * 2 + 1], kk.y, z1);
                        }
                        float a0, a1, b0, b1;
                        unpack2(z0, a0, a1);
                        unpack2(z1, b0, b1);
                        s[c] = (a0 + b0) + (a1 + b1);
                        cmax = fmaxf(cmax, s[c]);
                    }
                }
            }
            if (cmax > -INFINITY) {
                float mnew = fmaxf(mrow, cmax);
                float cscale = __expf(mrow - mnew);
                mrow = mnew;
                l *= cscale;
                u64 cs2 = pack2(cscale, cscale);
#pragma unroll
                for (int d = 0; d < 16; d++) acc2[d] = mul2(acc2[d], cs2);
#pragma unroll
                for (int c = 0; c < 8; c++) {
                    float p = __expf(s[c] - mnew);
                    l += p;
                    u64 pp = pack2(p, p);
                    const ulonglong2* vr = (const ulonglong2*)&Vs[(jc + c) * KS_STR];
#pragma unroll
                    for (int d8 = 0; d8 < 8; d8++) {
                        ulonglong2 vv = vr[d8];
                        acc2[d8 * 2]     = fma2(pp, vv.x, acc2[d8 * 2]);
                        acc2[d8 * 2 + 1] = fma2(pp, vv.y, acc2[d8 * 2 + 1]);
                    }
                }
            }
        }
    }

    float inv = 1.0f / l;
    float* orow = g_ao + ((size_t)(b * T + i)) * E + h * HD;
#pragma unroll
    for (int d8 = 0; d8 < 8; d8++) {
        float x0, x1, x2, x3;
        unpack2(acc2[d8 * 2],     x0, x1);
        unpack2(acc2[d8 * 2 + 1], x2, x3);
        float4 o;
        o.x = x0 * inv; o.y = x1 * inv; o.z = x2 * inv; o.w = x3 * inv;
        *(float4*)(orow + d8 * 4) = o;
    }
}

// ---------------- launch -----------------------------------------------------
extern "C" void kernel_launch(void* const* d_in, const int* in_sizes, int n_in,
                              void* d_out, int out_size) {
    const float* query = (const float*)d_in[0];
    const float* key_  = (const float*)d_in[1];
    const float* value = (const float*)d_in[2];
    const float* Wq = (const float*)d_in[3];
    const float* bq = (const float*)d_in[4];
    const float* Wk = (const float*)d_in[5];
    const float* bk = (const float*)d_in[6];
    const float* Wv = (const float*)d_in[7];
    const float* bv = (const float*)d_in[8];
    const float* Wo = (const float*)d_in[9];
    const float* bo = (const float*)d_in[10];
    const float* temperature = (const float*)d_in[11];
    const int* wsize = (const int*)d_in[12];
    const int* gnum  = (const int*)d_in[13];
    float* out = (float*)d_out;

    int E = in_sizes[4];                 // 512
    int B = B_CONST;
    int T = in_sizes[0] / (B * E);       // 2048
    int S = in_sizes[1] / (B * E);       // 2048
    int M = B * T;                       // 4096
    int hd = E / H_NUM;

    float *qb, *kb, *vb, *aob;
    cudaGetSymbolAddress((void**)&qb,  g_q);
    cudaGetSymbolAddress((void**)&kb,  g_k);
    cudaGetSymbolAddress((void**)&vb,  g_v);
    cudaGetSymbolAddress((void**)&aob, g_ao);

    glist_kernel<<<1, 32>>>(S, gnum);

    cudaFuncSetAttribute(qkv_gemm_kernel,
                         cudaFuncAttributeMaxDynamicSharedMemorySize, GEMM_SMEM);
    cudaFuncSetAttribute(oproj_gemm_kernel,
                         cudaFuncAttributeMaxDynamicSharedMemorySize, GEMM_SMEM);

    float scaling = 1.0f / sqrtf((float)hd);
    dim3 qkv_grid(E / BNG, M / BMG, 3);          // (8, 32, 3)
    qkv_gemm_kernel<<<qkv_grid, 256, GEMM_SMEM>>>(
        query, key_, value, Wq, Wk, Wv, bq, bk, bv,
        qb, kb, vb, M, E, E, scaling, temperature);

    cudaFuncSetAttribute(sparse_attn_kernel,
                         cudaFuncAttributeMaxDynamicSharedMemorySize, ATT_SMEM);
    sparse_attn_kernel<<<dim3(T / AT_BM, H_NUM, B), 128, ATT_SMEM>>>(T, S, E, wsize);

    dim3 ogrid(E / BNG, M / BMG);                // (8, 32)
    oproj_gemm_kernel<<<ogrid, 256, GEMM_SMEM>>>(aob, Wo, bo, out, M, E, E);
}